// round 9
// baseline (speedup 1.0000x reference)
#include <cuda_runtime.h>

// Problem constants
#define NCH   8192
#define NTT   4096
#define NLAGS 103
#define RAWS  112
#define XCOR_N (NCH * NLAGS)

// Stage-1 tiling: 8 warps x 14 lags = 112 padded lags. Each lane owns a
// contiguous 136-t range (grid padded to 4352 t); 17 steps of 8 t.
#define LPW    14
#define NW     8
#define T1     256
#define TPL    136
#define NSTEPS 17
#define AREG   252            // a region floats/lane (63 chunks, odd mod 8)
#define BREG   140            // b region floats/lane (35 chunks, odd mod 8)
#define A_TOT  (32 * AREG)    // 8064 floats
#define B_TOT  (32 * BREG)    // 4480 floats
#define SMEM_SZ ((A_TOT + 2 * B_TOT) * 4)   // 68096 B -> 3 blocks/SM

// Raw xcorr scratch: 8192 x 112 f32 (~3.67 MB, L2-resident)
__device__ float g_raw[(size_t)NCH * RAWS];

__device__ __forceinline__ void fma2(unsigned long long& d,
                                     unsigned long long a, unsigned long long b) {
    asm("fma.rn.f32x2 %0, %1, %2, %0;" : "+l"(d) : "l"(a), "l"(b));
}
__device__ __forceinline__ void unpack2(unsigned long long v, float& lo, float& hi) {
    asm("mov.b64 {%0, %1}, %2;" : "=f"(lo), "=f"(hi) : "l"(v));
}
__device__ __forceinline__ void lds_v2u64(unsigned long long& a, unsigned long long& b,
                                          unsigned addr) {
    asm volatile("ld.shared.v2.u64 {%0, %1}, [%2];" : "=l"(a), "=l"(b) : "r"(addr));
}
__device__ __forceinline__ unsigned smem_u32(const void* p) {
    unsigned r;
    asm("{ .reg .u64 t; cvta.to.shared.u64 t, %1; cvt.u32.u64 %0, t; }" : "=r"(r) : "l"(p));
    return r;
}

// One step: 8 new t. Loads 4 new a-pairs into the rotating 12-pair window,
// 4 b-pairs, 4 bs-pairs; issues 56 FFMA2 (7 even lags x4 + 7 odd lags x4).
// R = step mod 3 (window rotation), D0 = warp lag-base misalignment (0 or 1).
template<int R, int D0>
__device__ __forceinline__ void do_step(unsigned long long (&A2)[12],
                                        unsigned long long (&accE)[7],
                                        unsigned long long (&accO)[7],
                                        unsigned& aP, unsigned& bP, unsigned& sP)
{
    unsigned long long b2[4], s2[4];
    lds_v2u64(A2[(4 * R + 8) % 12],  A2[(4 * R + 9) % 12],  aP);
    lds_v2u64(A2[(4 * R + 10) % 12], A2[(4 * R + 11) % 12], aP + 16);
    lds_v2u64(b2[0], b2[1], bP);
    lds_v2u64(b2[2], b2[3], bP + 16);
    lds_v2u64(s2[0], s2[1], sP);
    lds_v2u64(s2[2], s2[3], sP + 16);
#pragma unroll
    for (int k = 0; k < 4; ++k) {
#pragma unroll
        for (int e = 0; e < 7; ++e) {
            fma2(accE[e], A2[(4 * R + D0 + e + k) % 12], b2[k]);
            fma2(accO[e], A2[(4 * R + D0 + e + k) % 12], s2[k]);
        }
    }
    aP += 32; bP += 32; sP += 32;
}

template<int D0>
__device__ __forceinline__ void mainloop(unsigned aAddr, unsigned bAddr, unsigned sAddr,
                                         float* outRow, int lane)
{
    unsigned long long A2[12];
    unsigned long long accE[7], accO[7];
#pragma unroll
    for (int e = 0; e < 7; ++e) { accE[e] = 0ull; accO[e] = 0ull; }

    // Preload first 8 pairs (16 floats) of the window.
    lds_v2u64(A2[0], A2[1], aAddr);
    lds_v2u64(A2[2], A2[3], aAddr + 16);
    lds_v2u64(A2[4], A2[5], aAddr + 32);
    lds_v2u64(A2[6], A2[7], aAddr + 48);
    unsigned aP = aAddr + 64;
    unsigned bP = bAddr, sP = sAddr;

    // 17 steps = 5 x (rotation 0,1,2) + rotation 0,1
#pragma unroll 1
    for (int m = 0; m < 5; ++m) {
        do_step<0, D0>(A2, accE, accO, aP, bP, sP);
        do_step<1, D0>(A2, accE, accO, aP, bP, sP);
        do_step<2, D0>(A2, accE, accO, aP, bP, sP);
    }
    do_step<0, D0>(A2, accE, accO, aP, bP, sP);
    do_step<1, D0>(A2, accE, accO, aP, bP, sP);

    // Combine even/odd-t halves, reduce over lanes, lane 0 writes 14 lags.
    float res[LPW];
#pragma unroll
    for (int e = 0; e < 7; ++e) {
        float lo, hi;
        unpack2(accE[e], lo, hi); res[2 * e]     = lo + hi;
        unpack2(accO[e], lo, hi); res[2 * e + 1] = lo + hi;
    }
#pragma unroll
    for (int j = 0; j < LPW; ++j) {
#pragma unroll
        for (int o = 16; o > 0; o >>= 1)
            res[j] += __shfl_xor_sync(0xffffffffu, res[j], o);
    }
    if (lane == 0) {
#pragma unroll
        for (int j = 0; j < LPW; ++j) outRow[j] = res[j];
    }
}

// ---------------------------------------------------------------------------
// Stage 1: R[c][l] = sum_t d1pad[t+l] * d2[t], l in [0,112), d1pad = d1
// shifted by 51 with zero pad. Grid padded to 4352 t (zeros beyond 4096).
// Odd lags via bs[i] = b[i-1]: R[m+1] = sum_s a[m+s]*bs[s] on the same grid.
// ---------------------------------------------------------------------------
__global__ __launch_bounds__(T1, 3)
void xcorr_stage1(const float* __restrict__ d1, const float* __restrict__ d2)
{
    extern __shared__ __align__(16) float sm[];
    float* aR = sm;                   // [32][AREG]: aR[l][j] = d1pad[136*l + j]
    float* bR = sm + A_TOT;           // [32][BREG]: bR[l][j] = b[136*l + j]
    float* sR = sm + A_TOT + B_TOT;   // [32][BREG]: sR[l][j] = b[136*l + j - 1]

    const int c   = blockIdx.x;
    const int tid = threadIdx.x;
    const float* __restrict__ r1 = d1 + (size_t)c * NTT;
    const float* __restrict__ r2 = d2 + (size_t)c * NTT;

    // Fill per-lane regions (coalesced: consecutive tid -> consecutive gmem).
#pragma unroll 1
    for (int l = 0; l < 32; ++l) {
        const int ibase = TPL * l;
        if (tid < AREG) {
            const int i = ibase + tid;     // d1pad index
            aR[l * AREG + tid] = (i >= 51 && i < 51 + NTT) ? r1[i - 51] : 0.0f;
        }
        if (tid < BREG) {
            const int i = ibase + tid;
            bR[l * BREG + tid] = (i < NTT) ? r2[i] : 0.0f;
            sR[l * BREG + tid] = (i >= 1 && i <= NTT) ? r2[i - 1] : 0.0f;
        }
    }
    __syncthreads();

    const int w  = tid >> 5;
    const int ln = tid & 31;
    const int lb = w * LPW;            // lag base: 0,14,...,98
    const int wBase = lb & ~3;         // 16B-aligned window base; D0 = (lb-wBase)/2

    const unsigned base  = smem_u32(sm);
    const unsigned aAddr = base + (unsigned)(ln * AREG + wBase) * 4u;
    const unsigned bAddr = base + (unsigned)(A_TOT + ln * BREG) * 4u;
    const unsigned sAddr = base + (unsigned)(A_TOT + B_TOT + ln * BREG) * 4u;

    float* outRow = g_raw + (size_t)c * RAWS + lb;
    if (w & 1) mainloop<1>(aAddr, bAddr, sAddr, outRow, ln);
    else       mainloop<0>(aAddr, bAddr, sAddr, outRow, ln);
}

// ---------------------------------------------------------------------------
// Stage 2: moving average over channels (window [c-10, c+9], zero-padded),
// then per-channel argmax|R| / max / min / tmax. Sliding ring over 8 channels.
// ---------------------------------------------------------------------------
#define CPB 8
__global__ __launch_bounds__(128)
void xcorr_stage2(float* __restrict__ out)
{
    __shared__ float sh[CPB][NLAGS + 1];
    const int c0  = blockIdx.x * CPB;
    const int tid = threadIdx.x;

    if (tid < NLAGS) {
        float ring[20];
        float s = 0.0f;
#pragma unroll
        for (int i = 0; i < CPB + 19; ++i) {
            const int ch = c0 - 10 + i;
            float x = 0.0f;
            if (ch >= 0 && ch < NCH) x = g_raw[(size_t)ch * RAWS + tid];
            s += x;
            if (i >= 20) s -= ring[i % 20];
            ring[i % 20] = x;
            const int cc = i - 19;
            if (cc >= 0) {
                const float m = s * (1.0f / 20.0f);
                sh[cc][tid] = m;
                out[(size_t)(c0 + cc) * NLAGS + tid] = m;
            }
        }
    }
    __syncthreads();

    const int warp = tid >> 5;
    const int lane = tid & 31;

    for (int cc = warp; cc < CPB; cc += 4) {
        float bestAbs = -1.0f;
        int   bestIdx = 0;
        float bestVal = 0.0f;
        float vpos = -3.402823466e38f;
        float vneg =  3.402823466e38f;

        for (int l = lane; l < NLAGS; l += 32) {
            const float v  = sh[cc][l];
            const float av = fabsf(v);
            if (av > bestAbs) { bestAbs = av; bestIdx = l; bestVal = v; }
            vpos = fmaxf(vpos, v);
            vneg = fminf(vneg, v);
        }
#pragma unroll
        for (int o = 16; o > 0; o >>= 1) {
            const float oa = __shfl_down_sync(0xffffffffu, bestAbs, o);
            const int   oi = __shfl_down_sync(0xffffffffu, bestIdx, o);
            const float ov = __shfl_down_sync(0xffffffffu, bestVal, o);
            if (oa > bestAbs || (oa == bestAbs && oi < bestIdx)) {
                bestAbs = oa; bestIdx = oi; bestVal = ov;
            }
            vpos = fmaxf(vpos, __shfl_down_sync(0xffffffffu, vpos, o));
            vneg = fminf(vneg, __shfl_down_sync(0xffffffffu, vneg, o));
        }

        if (lane == 0) {
            const int   ch    = c0 + cc;
            const float vside = (bestVal >= 0.0f) ? vneg : vpos;
            out[(size_t)XCOR_N + ch]           = bestVal;
            out[(size_t)XCOR_N + NCH + ch]     = vside;
            out[(size_t)XCOR_N + 2 * NCH + ch] = (float)(bestIdx - 51) * 0.01f;
        }
    }
}

// ---------------------------------------------------------------------------
// kernel_launch: inputs: data1 (f32, NC*NT), data2 (f32, NC*NT), event1,
// event2 (i32, unused by the reference).
// ---------------------------------------------------------------------------
extern "C" void kernel_launch(void* const* d_in, const int* in_sizes, int n_in,
                              void* d_out, int out_size)
{
    const float* data1 = (const float*)d_in[0];
    const float* data2 = (const float*)d_in[1];
    float* out = (float*)d_out;

    cudaFuncSetAttribute(xcorr_stage1,
                         cudaFuncAttributeMaxDynamicSharedMemorySize, SMEM_SZ);

    xcorr_stage1<<<NCH, T1, SMEM_SZ>>>(data1, data2);
    xcorr_stage2<<<NCH / CPB, 128>>>(out);
}

// round 10
// speedup vs baseline: 2.8307x; 2.8307x over previous
#include <cuda_runtime.h>

// Problem constants
#define NCH   8192
#define NTT   4096
#define NLAGS 103
#define RAWS  112
#define XCOR_N (NCH * NLAGS)

// Stage-1: 4 warps/block; lag slots {0..27, 28..55, 56..83, 84..103}.
// Slot rotated per block for SMSP load balance. Scalar FFMA (rt=2 ceiling).
#define T1    128
#define APAD  4208     // 51 zero pad + 4096 + tail pad
#define SMEM1 ((APAD + NTT) * 4)

// Raw xcorr scratch: 8192 x 112 f32 (~3.67 MB, L2-resident)
__device__ float g_raw[(size_t)NCH * RAWS];

// ---------------------------------------------------------------------------
// Per-warp correlation over L lags starting at (16B-aligned) float offset lb.
// Lane handles 4 consecutive t per iter; 32 iters cover 4096 t.
// ---------------------------------------------------------------------------
template<int L>
__device__ __forceinline__ void corr_warp(const float* __restrict__ a_sm,
                                          const float* __restrict__ b_sm,
                                          int lane, int lb,
                                          float* __restrict__ outRow)
{
    constexpr int NV = (L + 3 + 3) / 4;   // float4 loads covering L+3 floats

    float acc[L];
#pragma unroll
    for (int j = 0; j < L; ++j) acc[j] = 0.0f;

    const float* __restrict__ ap = a_sm + lb;

#pragma unroll 1
    for (int it = 0; it < 32; ++it) {
        const int t0 = it * 128 + lane * 4;

        float aw[NV * 4];
#pragma unroll
        for (int v = 0; v < NV; ++v) {
            const float4 w = *reinterpret_cast<const float4*>(ap + t0 + 4 * v);
            aw[4 * v + 0] = w.x; aw[4 * v + 1] = w.y;
            aw[4 * v + 2] = w.z; aw[4 * v + 3] = w.w;
        }
        const float4 b4 = *reinterpret_cast<const float4*>(b_sm + t0);
        float bv[4];
        bv[0] = b4.x; bv[1] = b4.y; bv[2] = b4.z; bv[3] = b4.w;

#pragma unroll
        for (int k = 0; k < 4; ++k) {
#pragma unroll
            for (int j = 0; j < L; ++j) {
                acc[j] = fmaf(aw[j + k], bv[k], acc[j]);
            }
        }
    }

    // Lane reduction over t; lane 0 writes L lags.
#pragma unroll
    for (int j = 0; j < L; ++j) {
#pragma unroll
        for (int o = 16; o > 0; o >>= 1)
            acc[j] += __shfl_xor_sync(0xffffffffu, acc[j], o);
    }
    if (lane == 0) {
#pragma unroll
        for (int j = 0; j < L; ++j) outRow[j] = acc[j];
    }
}

// ---------------------------------------------------------------------------
// Stage 1: R[c][l] = sum_t d1pad[t+l] * d2[t], l in [0,104), where
// d1pad = d1 shifted +51 with zero pad. One block per channel, 128 threads.
// ---------------------------------------------------------------------------
__global__ __launch_bounds__(T1, 6)
void xcorr_stage1(const float* __restrict__ d1, const float* __restrict__ d2)
{
    extern __shared__ __align__(16) float sm[];
    float* a_sm = sm;            // [APAD]
    float* b_sm = sm + APAD;     // [NTT]

    const int c   = blockIdx.x;
    const int tid = threadIdx.x;

    const float* __restrict__ r1 = d1 + (size_t)c * NTT;
    const float* __restrict__ r2 = d2 + (size_t)c * NTT;

    // Zero pads
    for (int i = tid; i < 51; i += T1) a_sm[i] = 0.0f;
    for (int i = 51 + NTT + tid; i < APAD; i += T1) a_sm[i] = 0.0f;

    // Bulk fill: vectorized global loads; scalar stores for the 51-shifted a.
    for (int k = tid; k < NTT / 4; k += T1) {
        const float4 v1 = reinterpret_cast<const float4*>(r1)[k];
        a_sm[51 + 4 * k + 0] = v1.x;
        a_sm[51 + 4 * k + 1] = v1.y;
        a_sm[51 + 4 * k + 2] = v1.z;
        a_sm[51 + 4 * k + 3] = v1.w;
        reinterpret_cast<float4*>(b_sm)[k] = reinterpret_cast<const float4*>(r2)[k];
    }
    __syncthreads();

    const int warp = tid >> 5;
    const int lane = tid & 31;
    // Rotate lag-slot assignment across blocks so the light slot (3) moves
    // between SMSPs: slot = (warp + bid) & 3.
    const int slot = (warp + blockIdx.x) & 3;

    if (slot < 3) {
        const int lb = slot * 28;
        corr_warp<28>(a_sm, b_sm, lane, lb, g_raw + (size_t)c * RAWS + lb);
    } else {
        corr_warp<20>(a_sm, b_sm, lane, 84, g_raw + (size_t)c * RAWS + 84);
    }
}

// ---------------------------------------------------------------------------
// Stage 2: moving average over channels (window [c-10, c+9], zero-padded),
// then per-channel argmax|R| / max / min / tmax. Sliding ring over 8 channels.
// ---------------------------------------------------------------------------
#define CPB 8
__global__ __launch_bounds__(128)
void xcorr_stage2(float* __restrict__ out)
{
    __shared__ float sh[CPB][NLAGS + 1];
    const int c0  = blockIdx.x * CPB;
    const int tid = threadIdx.x;

    if (tid < NLAGS) {
        float ring[20];
        float s = 0.0f;
#pragma unroll
        for (int i = 0; i < CPB + 19; ++i) {
            const int ch = c0 - 10 + i;
            float x = 0.0f;
            if (ch >= 0 && ch < NCH) x = g_raw[(size_t)ch * RAWS + tid];
            s += x;
            if (i >= 20) s -= ring[i % 20];
            ring[i % 20] = x;
            const int cc = i - 19;
            if (cc >= 0) {
                const float m = s * (1.0f / 20.0f);
                sh[cc][tid] = m;
                out[(size_t)(c0 + cc) * NLAGS + tid] = m;
            }
        }
    }
    __syncthreads();

    const int warp = tid >> 5;
    const int lane = tid & 31;

    for (int cc = warp; cc < CPB; cc += 4) {
        float bestAbs = -1.0f;
        int   bestIdx = 0;
        float bestVal = 0.0f;
        float vpos = -3.402823466e38f;
        float vneg =  3.402823466e38f;

        for (int l = lane; l < NLAGS; l += 32) {
            const float v  = sh[cc][l];
            const float av = fabsf(v);
            if (av > bestAbs) { bestAbs = av; bestIdx = l; bestVal = v; }
            vpos = fmaxf(vpos, v);
            vneg = fminf(vneg, v);
        }
#pragma unroll
        for (int o = 16; o > 0; o >>= 1) {
            const float oa = __shfl_down_sync(0xffffffffu, bestAbs, o);
            const int   oi = __shfl_down_sync(0xffffffffu, bestIdx, o);
            const float ov = __shfl_down_sync(0xffffffffu, bestVal, o);
            if (oa > bestAbs || (oa == bestAbs && oi < bestIdx)) {
                bestAbs = oa; bestIdx = oi; bestVal = ov;
            }
            vpos = fmaxf(vpos, __shfl_down_sync(0xffffffffu, vpos, o));
            vneg = fminf(vneg, __shfl_down_sync(0xffffffffu, vneg, o));
        }

        if (lane == 0) {
            const int   ch    = c0 + cc;
            const float vside = (bestVal >= 0.0f) ? vneg : vpos;
            out[(size_t)XCOR_N + ch]           = bestVal;
            out[(size_t)XCOR_N + NCH + ch]     = vside;
            out[(size_t)XCOR_N + 2 * NCH + ch] = (float)(bestIdx - 51) * 0.01f;
        }
    }
}

// ---------------------------------------------------------------------------
// kernel_launch: inputs: data1 (f32, NC*NT), data2 (f32, NC*NT), event1,
// event2 (i32, unused by the reference).
// ---------------------------------------------------------------------------
extern "C" void kernel_launch(void* const* d_in, const int* in_sizes, int n_in,
                              void* d_out, int out_size)
{
    const float* data1 = (const float*)d_in[0];
    const float* data2 = (const float*)d_in[1];
    float* out = (float*)d_out;

    xcorr_stage1<<<NCH, T1, SMEM1>>>(data1, data2);
    xcorr_stage2<<<NCH / CPB, 128>>>(out);
}

// round 11
// speedup vs baseline: 3.0170x; 1.0658x over previous
#include <cuda_runtime.h>

// Problem constants
#define NCH   8192
#define NTT   4096
#define NLAGS 103
#define RAWS  112
#define XCOR_N (NCH * NLAGS)

// Stage-1: 4 warps/block; exact lag split {26,26,26,25}, bases {0,26,52,78}.
// d1 stored UNshifted at float offset 64 => d1pad[x] = a_sm[x + 13].
// Per-slot aligned window base B=(lb+13)&~3, compile-time offset OFF=(lb+13)&3.
#define T1     128
#define A_OFF  64            // where d1[0] lands in a_sm (16B aligned)
#define A_SZ   4224          // covers max read index 4211
#define SMEM1  ((A_SZ + NTT) * 4)

// Raw xcorr scratch: 8192 x 112 f32 (~3.67 MB, L2-resident)
__device__ float g_raw[(size_t)NCH * RAWS];

// ---------------------------------------------------------------------------
// Per-warp correlation: L lags, window offset OFF from the aligned base a_al.
// Lane handles 4 consecutive t per iter; 32 iters cover 4096 t.
// acc[j] = sum_t a_al[t + OFF + j + k] * b[t + k]  (k = 0..3 within the iter)
// ---------------------------------------------------------------------------
template<int L, int OFF>
__device__ __forceinline__ void corr_warp(const float* __restrict__ a_al,
                                          const float* __restrict__ b_sm,
                                          int lane,
                                          float* __restrict__ outRow)
{
    constexpr int NV = (OFF + L + 3 + 3) / 4;   // float4 loads covering window

    float acc[L];
#pragma unroll
    for (int j = 0; j < L; ++j) acc[j] = 0.0f;

#pragma unroll 1
    for (int it = 0; it < 32; ++it) {
        const int t0 = it * 128 + lane * 4;

        float aw[NV * 4];
#pragma unroll
        for (int v = 0; v < NV; ++v) {
            const float4 w = *reinterpret_cast<const float4*>(a_al + t0 + 4 * v);
            aw[4 * v + 0] = w.x; aw[4 * v + 1] = w.y;
            aw[4 * v + 2] = w.z; aw[4 * v + 3] = w.w;
        }
        const float4 b4 = *reinterpret_cast<const float4*>(b_sm + t0);
        float bv[4];
        bv[0] = b4.x; bv[1] = b4.y; bv[2] = b4.z; bv[3] = b4.w;

#pragma unroll
        for (int k = 0; k < 4; ++k) {
#pragma unroll
            for (int j = 0; j < L; ++j) {
                acc[j] = fmaf(aw[OFF + j + k], bv[k], acc[j]);
            }
        }
    }

    // Lane reduction over t; lane 0 writes L lags.
#pragma unroll
    for (int j = 0; j < L; ++j) {
#pragma unroll
        for (int o = 16; o > 0; o >>= 1)
            acc[j] += __shfl_xor_sync(0xffffffffu, acc[j], o);
    }
    if (lane == 0) {
#pragma unroll
        for (int j = 0; j < L; ++j) outRow[j] = acc[j];
    }
}

// ---------------------------------------------------------------------------
// Stage 1: R[c][l] = sum_t d1pad[t+l] * d2[t], l in [0,103), with
// d1pad[x] = d1[x-51] (zero outside). One block per channel, 128 threads.
// Slot -> (lag base lb, L, aligned base B=(lb+13)&~3, OFF=(lb+13)&3):
//   0: lb=0,  L=26, B=12, OFF=1
//   1: lb=26, L=26, B=36, OFF=3
//   2: lb=52, L=26, B=64, OFF=1
//   3: lb=78, L=25, B=88, OFF=3
// ---------------------------------------------------------------------------
__global__ __launch_bounds__(T1, 6)
void xcorr_stage1(const float* __restrict__ d1, const float* __restrict__ d2)
{
    extern __shared__ __align__(16) float sm[];
    float* a_sm = sm;            // [A_SZ]; d1 at [A_OFF, A_OFF+NTT)
    float* b_sm = sm + A_SZ;     // [NTT]

    const int c   = blockIdx.x;
    const int tid = threadIdx.x;

    const float* __restrict__ r1 = d1 + (size_t)c * NTT;
    const float* __restrict__ r2 = d2 + (size_t)c * NTT;

    // Zero pads: [0, A_OFF) and [A_OFF+NTT, A_SZ)
    for (int i = tid; i < A_OFF / 4; i += T1)
        reinterpret_cast<float4*>(a_sm)[i] = make_float4(0.f, 0.f, 0.f, 0.f);
    for (int i = tid; i < (A_SZ - A_OFF - NTT) / 4; i += T1)
        reinterpret_cast<float4*>(a_sm + A_OFF + NTT)[i] = make_float4(0.f, 0.f, 0.f, 0.f);

    // Bulk fill: pure float4 loads and stores (a unshifted at offset 64).
    for (int k = tid; k < NTT / 4; k += T1) {
        reinterpret_cast<float4*>(a_sm + A_OFF)[k] = reinterpret_cast<const float4*>(r1)[k];
        reinterpret_cast<float4*>(b_sm)[k]         = reinterpret_cast<const float4*>(r2)[k];
    }
    __syncthreads();

    const int warp = tid >> 5;
    const int lane = tid & 31;
    // Rotate slot assignment across blocks for SMSP load balance.
    const int slot = (warp + blockIdx.x) & 3;

    float* row = g_raw + (size_t)c * RAWS;
    switch (slot) {
        case 0: corr_warp<26, 1>(a_sm + 12, b_sm, lane, row + 0);  break;
        case 1: corr_warp<26, 3>(a_sm + 36, b_sm, lane, row + 26); break;
        case 2: corr_warp<26, 1>(a_sm + 64, b_sm, lane, row + 52); break;
        default: corr_warp<25, 3>(a_sm + 88, b_sm, lane, row + 78); break;
    }
}

// ---------------------------------------------------------------------------
// Stage 2: moving average over channels (window [c-10, c+9], zero-padded),
// then per-channel argmax|R| / max / min / tmax.
// 8 channels per block; each thread prefetches all 27 halo values (MLP) then
// computes the sliding sum in registers (no serial L2 chain).
// ---------------------------------------------------------------------------
#define CPB 8
__global__ __launch_bounds__(128)
void xcorr_stage2(float* __restrict__ out)
{
    __shared__ float sh[CPB][NLAGS + 1];
    const int c0  = blockIdx.x * CPB;
    const int tid = threadIdx.x;

    if (tid < NLAGS) {
        float x[CPB + 19];
#pragma unroll
        for (int i = 0; i < CPB + 19; ++i) {
            const int ch = c0 - 10 + i;
            x[i] = (ch >= 0 && ch < NCH) ? g_raw[(size_t)ch * RAWS + tid] : 0.0f;
        }
        float s = 0.0f;
#pragma unroll
        for (int i = 0; i < 20; ++i) s += x[i];
#pragma unroll
        for (int cc = 0; cc < CPB; ++cc) {
            const float m = s * (1.0f / 20.0f);
            sh[cc][tid] = m;
            out[(size_t)(c0 + cc) * NLAGS + tid] = m;
            if (cc + 1 < CPB) s += x[cc + 20] - x[cc];
        }
    }
    __syncthreads();

    const int warp = tid >> 5;
    const int lane = tid & 31;

    for (int cc = warp; cc < CPB; cc += 4) {
        float bestAbs = -1.0f;
        int   bestIdx = 0;
        float bestVal = 0.0f;
        float vpos = -3.402823466e38f;
        float vneg =  3.402823466e38f;

        for (int l = lane; l < NLAGS; l += 32) {
            const float v  = sh[cc][l];
            const float av = fabsf(v);
            if (av > bestAbs) { bestAbs = av; bestIdx = l; bestVal = v; }
            vpos = fmaxf(vpos, v);
            vneg = fminf(vneg, v);
        }
#pragma unroll
        for (int o = 16; o > 0; o >>= 1) {
            const float oa = __shfl_down_sync(0xffffffffu, bestAbs, o);
            const int   oi = __shfl_down_sync(0xffffffffu, bestIdx, o);
            const float ov = __shfl_down_sync(0xffffffffu, bestVal, o);
            if (oa > bestAbs || (oa == bestAbs && oi < bestIdx)) {
                bestAbs = oa; bestIdx = oi; bestVal = ov;
            }
            vpos = fmaxf(vpos, __shfl_down_sync(0xffffffffu, vpos, o));
            vneg = fminf(vneg, __shfl_down_sync(0xffffffffu, vneg, o));
        }

        if (lane == 0) {
            const int   ch    = c0 + cc;
            const float vside = (bestVal >= 0.0f) ? vneg : vpos;
            out[(size_t)XCOR_N + ch]           = bestVal;
            out[(size_t)XCOR_N + NCH + ch]     = vside;
            out[(size_t)XCOR_N + 2 * NCH + ch] = (float)(bestIdx - 51) * 0.01f;
        }
    }
}

// ---------------------------------------------------------------------------
// kernel_launch: inputs: data1 (f32, NC*NT), data2 (f32, NC*NT), event1,
// event2 (i32, unused by the reference).
// ---------------------------------------------------------------------------
extern "C" void kernel_launch(void* const* d_in, const int* in_sizes, int n_in,
                              void* d_out, int out_size)
{
    const float* data1 = (const float*)d_in[0];
    const float* data2 = (const float*)d_in[1];
    float* out = (float*)d_out;

    xcorr_stage1<<<NCH, T1, SMEM1>>>(data1, data2);
    xcorr_stage2<<<NCH / CPB, 128>>>(out);
}